// round 13
// baseline (speedup 1.0000x reference)
#include <cuda_runtime.h>
#include <cuda_bf16.h>
#include <math.h>

#define Bn    8
#define Hn    384
#define Wn    384
#define HW    (Hn*Wn)
#define NPIX  (Bn*HW)
#define NCLS  4
#define EDIM  8
#define NINST 33
#define RUNS_PER_IMG (HW/16)          // 9216
#define RUNS_X       (Wn/16)          // 24
#define SEG_BLK_PER_IMG 36
#define SEG_BLOCKS   (SEG_BLK_PER_IMG*Bn)       // 288
#define SEM_BLOCKS   (NPIX/4/256)               // 1152
#define SEMA_BLOCKS  452                        // wave 1 = seg(288)+semA(452)=740
#define SEMB_BLOCKS  (SEM_BLOCKS - SEMA_BLOCKS) // 700
#define HR_PER_IMG   (RUNS_PER_IMG*2)           // 18432 half-runs
#define K2_BLK_PER_IMG (HR_PER_IMG/256)         // 72
#define K2_BLOCKS    (K2_BLK_PER_IMG*Bn)        // 576
#define TOTAL_BLOCKS (SEG_BLOCKS + SEM_BLOCKS + K2_BLOCKS + 1)   // 2017

// ---------------- scratch ----------------------------------------------------
struct Scr {
    double sem, a9, a3, a4;
    float  cnt [Bn*NINST];
    float  ws  [Bn*NINST];
    float  ew  [Bn*NINST*EDIM];
    float  pull[Bn*NINST];
    int    done_seg, done_sem, done_k2;
};
__device__ Scr g_s;
__device__ unsigned int g_runinfo[Bn*RUNS_PER_IMG];   // mask16 | label<<16 | uni<<31

__device__ __forceinline__ float warp_redf(float v){
    #pragma unroll
    for (int o = 16; o > 0; o >>= 1) v += __shfl_down_sync(0xffffffffu, v, o);
    return v;
}

__device__ __forceinline__ float bweight(const int* __restrict__ L, int y, int x, int l)
{
    int ym = y > 0 ? y-1 : 0, yp = y < Hn-1 ? y+1 : Hn-1;
    int xm = x > 0 ? x-1 : 0, xp = x < Wn-1 ? x+1 : Wn-1;
    const int* r0 = L + ym*Wn;
    const int* r1 = L + y *Wn;
    const int* r2 = L + yp*Wn;
    bool bd = (r0[xm]!=l) | (r0[x]!=l) | (r0[xp]!=l)
            | (r1[xm]!=l) |              (r1[xp]!=l)
            | (r2[xm]!=l) | (r2[x]!=l) | (r2[xp]!=l);
    return bd ? 10.0f : 1.0f;
}

__device__ __forceinline__ void spin_until(int* ctr, int target)
{
    if (threadIdx.x == 0) {
        while (atomicAdd(ctr, 0) < target) __nanosleep(64);
        __threadfence();
    }
    __syncthreads();
}

__device__ __forceinline__ void signal_done(int* ctr)
{
    __syncthreads();
    if (threadIdx.x == 0) { __threadfence(); atomicAdd(ctr, 1); }
}

__device__ __forceinline__ float l1f4(float4 a, float4 c)
{
    return fabsf(a.x-c.x)+fabsf(a.y-c.y)+fabsf(a.z-c.z)+fabsf(a.w-c.w);
}

// =============================================================================
// Block roles in scheduling order:
//   [0, 288)      seg     (retires in wave 1)
//   [288, 740)    semA    (fills rest of wave 1)
//   [740, 1316)   pull    (spins on seg; wave >=2 so spin passes instantly;
//                          L2-heavy embedding reads overlap semB's DRAM stream)
//   [1316, 2016)  semB
//   2016          finalize
// =============================================================================
__global__ void __launch_bounds__(256, 5)
K(const float* __restrict__ sem, const int* __restrict__ cl,
  const float* __restrict__ geo, const float* __restrict__ gd,
  const float* __restrict__ gg,  const float* __restrict__ gr,
  const int*   __restrict__ lbl, const float* __restrict__ emb,
  float* __restrict__ out, int out_size)
{
    int bid = blockIdx.x;

    // ======================= SEG =============================================
    if (bid < SEG_BLOCKS) {
        int b   = bid / SEG_BLK_PER_IMG;
        int blk = bid - b*SEG_BLK_PER_IMG;

        __shared__ float s_cnt[NINST], s_ws[NINST], s_ew[NINST*EDIM];
        for (int i = threadIdx.x; i < NINST; i += blockDim.x) { s_cnt[i]=0.f; s_ws[i]=0.f; }
        for (int i = threadIdx.x; i < NINST*EDIM; i += blockDim.x) s_ew[i]=0.f;
        __syncthreads();

        const int*   L = lbl + b*HW;
        const float* E = emb + (size_t)b*EDIM*HW;

        int r = blk*blockDim.x + threadIdx.x;
        int y  = r / RUNS_X;
        int x0 = (r - y*RUNS_X) * 16;
        int base = y*Wn + x0;

        const int*  rM = L + base;
        const int4* m4 = (const int4*)rM;
        int4 a0 = m4[0], a1 = m4[1], a2 = m4[2], a3 = m4[3];
        int l = a0.x;
        bool uni = (a0.y==l)&(a0.z==l)&(a0.w==l)
                 & (a1.x==l)&(a1.y==l)&(a1.z==l)&(a1.w==l)
                 & (a2.x==l)&(a2.y==l)&(a2.z==l)&(a2.w==l)
                 & (a3.x==l)&(a3.y==l)&(a3.z==l)&(a3.w==l);

        if (uni) {
            int ym = y > 0 ? y-1 : 0, yp = y < Hn-1 ? y+1 : Hn-1;
            const int* rT = L + ym*Wn + x0;
            const int* rB = L + yp*Wn + x0;
            const int4* t4 = (const int4*)rT;
            const int4* b4 = (const int4*)rB;
            unsigned int bad = 0;
            #pragma unroll
            for (int k = 0; k < 4; k++) {
                int4 tt = t4[k];
                bad |= ((unsigned)(tt.x!=l)<<(1+4*k)) | ((unsigned)(tt.y!=l)<<(2+4*k))
                     | ((unsigned)(tt.z!=l)<<(3+4*k)) | ((unsigned)(tt.w!=l)<<(4+4*k));
                int4 bb = b4[k];
                bad |= ((unsigned)(bb.x!=l)<<(1+4*k)) | ((unsigned)(bb.y!=l)<<(2+4*k))
                     | ((unsigned)(bb.z!=l)<<(3+4*k)) | ((unsigned)(bb.w!=l)<<(4+4*k));
            }
            int xl = (x0 > 0) ? -1 : 0;
            int xr = (x0+16 < Wn) ? 16 : 15;
            bad |= (unsigned)(rT[xl]!=l) | ((unsigned)(rT[xr]!=l)<<17);
            bad |= (unsigned)(rB[xl]!=l) | ((unsigned)(rB[xr]!=l)<<17);
            bad |= (unsigned)(rM[xl]!=l) | ((unsigned)(rM[xr]!=l)<<17);

            unsigned int mask = (bad | (bad>>1) | (bad>>2)) & 0xFFFFu;

            atomicAdd(&s_cnt[l], 16.0f);
            atomicAdd(&s_ws [l], 16.0f + 9.0f*(float)__popc(mask));
            #pragma unroll
            for (int c = 0; c < EDIM; c++) {
                const float4* Ep = (const float4*)(E + (size_t)c*HW + base);
                float4 e0 = Ep[0], e1 = Ep[1], e2 = Ep[2], e3 = Ep[3];
                float ev[16] = {e0.x,e0.y,e0.z,e0.w, e1.x,e1.y,e1.z,e1.w,
                                e2.x,e2.y,e2.z,e2.w, e3.x,e3.y,e3.z,e3.w};
                float acc = 0.f;
                #pragma unroll
                for (int i = 0; i < 16; i++)
                    acc += ev[i] * fmaf((float)((mask>>i)&1u), 9.0f, 1.0f);
                atomicAdd(&s_ew[l*EDIM+c], acc);
            }
            g_runinfo[b*RUNS_PER_IMG + r] = mask | ((unsigned)l<<16) | (1u<<31);
        } else {
            int ls[16] = {a0.x,a0.y,a0.z,a0.w, a1.x,a1.y,a1.z,a1.w,
                          a2.x,a2.y,a2.z,a2.w, a3.x,a3.y,a3.z,a3.w};
            unsigned int mask = 0;
            #pragma unroll 1
            for (int i = 0; i < 16; i++) {
                int li = ls[i];
                float w = bweight(L, y, x0+i, li);
                if (w > 1.f) mask |= (1u<<i);
                atomicAdd(&s_cnt[li], 1.0f);
                atomicAdd(&s_ws [li], w);
                for (int c = 0; c < EDIM; c++)
                    atomicAdd(&s_ew[li*EDIM+c], E[(size_t)c*HW + base + i] * w);
            }
            g_runinfo[b*RUNS_PER_IMG + r] = mask;
        }
        __syncthreads();
        for (int i = threadIdx.x; i < NINST; i += blockDim.x) {
            if (s_cnt[i] != 0.f) atomicAdd(&g_s.cnt[b*NINST+i], s_cnt[i]);
            if (s_ws [i] != 0.f) atomicAdd(&g_s.ws [b*NINST+i], s_ws [i]);
        }
        for (int i = threadIdx.x; i < NINST*EDIM; i += blockDim.x)
            if (s_ew[i] != 0.f) atomicAdd(&g_s.ew[b*NINST*EDIM+i], s_ew[i]);

        signal_done(&g_s.done_seg);
        return;
    }
    bid -= SEG_BLOCKS;

    // ---- resolve semA / pull / semB / fin ----
    int sembid = -1;
    if (bid < SEMA_BLOCKS) {
        sembid = bid;
    } else {
        int bid2 = bid - SEMA_BLOCKS;
        if (bid2 < K2_BLOCKS) {
            // ======================= PULL (waits on seg) =====================
            spin_until(&g_s.done_seg, SEG_BLOCKS);

            int b   = bid2 / K2_BLK_PER_IMG;
            int blk = bid2 - b*K2_BLK_PER_IMG;

            __shared__ float s_ctr[NINST*EDIM];
            __shared__ float s_pull[NINST];
            for (int i = threadIdx.x; i < NINST*EDIM; i += blockDim.x)
                s_ctr[i] = g_s.ew[b*NINST*EDIM + i] / (g_s.ws[b*NINST + (i>>3)] + 1e-8f);
            for (int i = threadIdx.x; i < NINST; i += blockDim.x) s_pull[i] = 0.f;
            __syncthreads();

            const float* E = emb + (size_t)b*EDIM*HW;

            int r8 = blk*blockDim.x + threadIdx.x;
            int y  = r8 / (2*RUNS_X);
            int x8 = (r8 - y*(2*RUNS_X)) * 8;
            int base = y*Wn + x8;

            unsigned int info = g_runinfo[b*RUNS_PER_IMG + y*RUNS_X + (x8>>4)];
            unsigned int mask8 = (info >> (((x8>>3)&1)*8)) & 0xFFu;

            if (info & (1u<<31)) {
                int l = (int)((info>>16) & 0x3Fu);
                float ss[8];
                #pragma unroll
                for (int i = 0; i < 8; i++) ss[i] = 0.f;
                #pragma unroll
                for (int c = 0; c < EDIM; c++) {
                    float ccv = s_ctr[l*EDIM+c];
                    const float4* Ep = (const float4*)(E + (size_t)c*HW + base);
                    float4 e0 = Ep[0], e1 = Ep[1];
                    float d0=e0.x-ccv, d1=e0.y-ccv, d2=e0.z-ccv, d3=e0.w-ccv;
                    float d4=e1.x-ccv, d5=e1.y-ccv, d6=e1.z-ccv, d7=e1.w-ccv;
                    ss[0]+=d0*d0; ss[1]+=d1*d1; ss[2]+=d2*d2; ss[3]+=d3*d3;
                    ss[4]+=d4*d4; ss[5]+=d5*d5; ss[6]+=d6*d6; ss[7]+=d7*d7;
                }
                float acc = 0.f;
                #pragma unroll
                for (int i = 0; i < 8; i++) {
                    float dist = sqrtf(fmaxf(ss[i], 1e-12f));
                    float t = fmaxf(dist - 0.5f, 0.f);
                    float w = fmaf((float)((mask8>>i)&1u), 9.0f, 1.0f);
                    acc += t*t*w;
                }
                atomicAdd(&s_pull[l], acc);
            } else {
                const int* Lp = lbl + b*HW + base;
                int4 L0 = ((const int4*)Lp)[0];
                int4 L1 = ((const int4*)Lp)[1];
                int ls[8] = {L0.x,L0.y,L0.z,L0.w, L1.x,L1.y,L1.z,L1.w};
                #pragma unroll 1
                for (int i = 0; i < 8; i++) {
                    int l = ls[i];
                    float ssv = 0.f;
                    for (int c = 0; c < EDIM; c++) {
                        float d = E[(size_t)c*HW + base + i] - s_ctr[l*EDIM+c];
                        ssv += d*d;
                    }
                    float dist = sqrtf(fmaxf(ssv, 1e-12f));
                    float t = fmaxf(dist - 0.5f, 0.f);
                    float w = fmaf((float)((mask8>>i)&1u), 9.0f, 1.0f);
                    atomicAdd(&s_pull[l], t*t*w);
                }
            }
            __syncthreads();
            for (int i = threadIdx.x; i < NINST; i += blockDim.x)
                if (s_pull[i] != 0.f) atomicAdd(&g_s.pull[b*NINST+i], s_pull[i]);

            signal_done(&g_s.done_k2);
            return;
        }
        bid2 -= K2_BLOCKS;
        if (bid2 < SEMB_BLOCKS) sembid = SEMA_BLOCKS + bid2;
        // else finalize (sembid == -1)
    }

    // ======================= SEMAFF ==========================================
    if (sembid >= 0) {
        int t  = sembid*blockDim.x + threadIdx.x;
        int H4 = HW/4;
        int b  = t / H4;
        int q4 = t - b*H4;
        size_t q = (size_t)q4 * 4;

        const float4* s4 = (const float4*)(sem + (size_t)b*NCLS*HW + q);
        float4 x0 = __ldcs(s4);
        float4 x1 = __ldcs(s4 + HW/4);
        float4 x2 = __ldcs(s4 + 2*(HW/4));
        float4 x3 = __ldcs(s4 + 3*(HW/4));
        int4 cc = __ldcs((const int4*)(cl + (size_t)b*HW + q));

        float s = 0.f;
        {
            float a[4][4] = {{x0.x,x1.x,x2.x,x3.x},{x0.y,x1.y,x2.y,x3.y},
                             {x0.z,x1.z,x2.z,x3.z},{x0.w,x1.w,x2.w,x3.w}};
            int   ci[4] = {cc.x, cc.y, cc.z, cc.w};
            #pragma unroll
            for (int j = 0; j < 4; j++) {
                float m = fmaxf(fmaxf(a[j][0],a[j][1]), fmaxf(a[j][2],a[j][3]));
                float sum = __expf(a[j][0]-m)+__expf(a[j][1]-m)
                          + __expf(a[j][2]-m)+__expf(a[j][3]-m);
                float lse = m + __logf(sum);
                int c = ci[j];
                float xc = (c==0) ? a[j][0] : ((c==1) ? a[j][1] : ((c==2) ? a[j][2] : a[j][3]));
                s += lse - xc;
            }
        }

        const float4* gp = (const float4*)(geo + (size_t)b*16*HW + q);
        const float4* dp = (const float4*)(gd  + (size_t)b*9 *HW + q);
        const float4* gp2= (const float4*)(gg  + (size_t)b*3 *HW + q);
        const float4* rp = (const float4*)(gr  + (size_t)b*4 *HW + q);
        float t9 = 0, t3 = 0, t4v = 0;
        #pragma unroll
        for (int i = 0; i < 9; i += 3) {
            float4 a0 = __ldcs(gp + (size_t)(i+0)*(HW/4));
            float4 a1 = __ldcs(gp + (size_t)(i+1)*(HW/4));
            float4 a2 = __ldcs(gp + (size_t)(i+2)*(HW/4));
            float4 c0 = __ldcs(dp + (size_t)(i+0)*(HW/4));
            float4 c1 = __ldcs(dp + (size_t)(i+1)*(HW/4));
            float4 c2 = __ldcs(dp + (size_t)(i+2)*(HW/4));
            t9 += l1f4(a0,c0) + l1f4(a1,c1) + l1f4(a2,c2);
        }
        {
            float4 a0 = __ldcs(gp + (size_t)9 *(HW/4));
            float4 a1 = __ldcs(gp + (size_t)10*(HW/4));
            float4 a2 = __ldcs(gp + (size_t)11*(HW/4));
            float4 c0 = __ldcs(gp2);
            float4 c1 = __ldcs(gp2 + (HW/4));
            float4 c2 = __ldcs(gp2 + 2*(HW/4));
            t3 = l1f4(a0,c0) + l1f4(a1,c1) + l1f4(a2,c2);
        }
        {
            float4 a0 = __ldcs(gp + (size_t)12*(HW/4));
            float4 a1 = __ldcs(gp + (size_t)13*(HW/4));
            float4 a2 = __ldcs(gp + (size_t)14*(HW/4));
            float4 a3 = __ldcs(gp + (size_t)15*(HW/4));
            float4 c0 = __ldcs(rp);
            float4 c1 = __ldcs(rp + (HW/4));
            float4 c2 = __ldcs(rp + 2*(HW/4));
            float4 c3 = __ldcs(rp + 3*(HW/4));
            t4v = l1f4(a0,c0) + l1f4(a1,c1) + l1f4(a2,c2) + l1f4(a3,c3);
        }

        __shared__ float sh[4][8];
        int lane = threadIdx.x & 31, wid = threadIdx.x >> 5;
        float v0 = warp_redf(s);
        float v1 = warp_redf(t9);
        float v2 = warp_redf(t3);
        float v3 = warp_redf(t4v);
        if (lane == 0) { sh[0][wid]=v0; sh[1][wid]=v1; sh[2][wid]=v2; sh[3][wid]=v3; }
        __syncthreads();
        if (wid == 0) {
            v0 = lane < 8 ? sh[0][lane] : 0.f;
            v1 = lane < 8 ? sh[1][lane] : 0.f;
            v2 = lane < 8 ? sh[2][lane] : 0.f;
            v3 = lane < 8 ? sh[3][lane] : 0.f;
            v0 = warp_redf(v0); v1 = warp_redf(v1); v2 = warp_redf(v2); v3 = warp_redf(v3);
            if (lane == 0) {
                atomicAdd(&g_s.sem, (double)v0); atomicAdd(&g_s.a9, (double)v1);
                atomicAdd(&g_s.a3, (double)v2);  atomicAdd(&g_s.a4, (double)v3);
            }
        }
        signal_done(&g_s.done_sem);
        return;
    }

    // ======================= FINALIZE ========================================
    spin_until(&g_s.done_sem, SEM_BLOCKS);
    spin_until(&g_s.done_k2,  K2_BLOCKS);

    __shared__ float s_ctr[Bn][NINST*EDIM];
    __shared__ float s_cnt[Bn][NINST];
    __shared__ float rp[Bn], rq[Bn], rn[Bn];
    __shared__ int   rpres[Bn];

    for (int i = threadIdx.x; i < Bn*NINST*EDIM; i += blockDim.x) {
        int b = i / (NINST*EDIM), k = i % (NINST*EDIM);
        s_ctr[b][k] = g_s.ew[i] / (g_s.ws[b*NINST + (k>>3)] + 1e-8f);
    }
    for (int i = threadIdx.x; i < Bn*NINST; i += blockDim.x)
        s_cnt[i/NINST][i%NINST] = g_s.cnt[i];
    __syncthreads();

    int wid = threadIdx.x >> 5, lane = threadIdx.x & 31;
    if (wid < Bn) {
        int b = wid;
        float pull = 0, norm = 0; int np = 0;
        for (int k = lane; k < NINST; k += 32) {
            bool pres = (k > 0) && (s_cnt[b][k] > 0.f);
            if (pres) {
                pull += g_s.pull[b*NINST+k] / fmaxf(s_cnt[b][k], 1.0f);
                float ssn = 0;
                #pragma unroll
                for (int c = 0; c < EDIM; c++) { float v = s_ctr[b][k*EDIM+c]; ssn += v*v; }
                norm += sqrtf(fmaxf(ssn, 1e-12f));
                np++;
            }
        }
        float push = 0; int npair = 0;
        for (int idx = lane; idx < NINST*NINST; idx += 32) {
            int i = idx / NINST, j = idx % NINST;
            if (j > i && i > 0 && s_cnt[b][i] > 0.f && s_cnt[b][j] > 0.f) {
                float ssd = 0;
                #pragma unroll
                for (int c = 0; c < EDIM; c++) {
                    float d = s_ctr[b][i*EDIM+c] - s_ctr[b][j*EDIM+c];
                    ssd += d*d;
                }
                float pd = sqrtf(fmaxf(ssd, 1e-12f));
                float t = fmaxf(3.0f - pd, 0.f);
                push += t*t; npair++;
            }
        }
        pull = warp_redf(pull); norm = warp_redf(norm); push = warp_redf(push);
        np   = __reduce_add_sync(0xffffffffu, np);
        npair= __reduce_add_sync(0xffffffffu, npair);
        if (lane == 0) {
            rp[b] = pull;
            rq[b] = push / fmaxf((float)npair, 1.0f);
            rn[b] = norm / fmaxf((float)np, 1.0f);
            rpres[b] = (np > 0) ? 1 : 0;
        }
    }
    __syncthreads();
    if (threadIdx.x == 0) {
        float pull = 0, push = 0, norm = 0; int n = 0;
        for (int bb = 0; bb < Bn; bb++) { pull += rp[bb]; push += rq[bb]; norm += rn[bb]; n += rpres[bb]; }
        float nn  = fmaxf((float)n, 1.0f);
        float ins = (pull + push + 0.001f*norm) / nn;
        float semv = (float)(g_s.sem / (double)NPIX);
        float aff  = (float)(g_s.a9/(double)((size_t)Bn*9*HW)
                           + g_s.a3/(double)((size_t)Bn*3*HW)
                           + g_s.a4/(double)((size_t)Bn*4*HW));
        out[0] = semv + aff + ins;
        if (out_size > 1) out[1] = semv;
        if (out_size > 2) out[2] = aff;
        if (out_size > 3) out[3] = ins;
    }
}

// ---------------- entry -------------------------------------------------------
extern "C" void kernel_launch(void* const* d_in, const int* in_sizes, int n_in,
                              void* d_out, int out_size)
{
    const float* sem  = (const float*)d_in[0];
    const int*   cl   = (const int*)  d_in[1];
    const float* inst = (const float*)d_in[2];
    const float* geo  = (const float*)d_in[3];
    const float* gd   = (const float*)d_in[4];
    const float* gg   = (const float*)d_in[5];
    const float* gr   = (const float*)d_in[6];
    const int*   lbl  = (const int*)  d_in[7];
    float* out = (float*)d_out;

    void* scr = nullptr;
    cudaGetSymbolAddress(&scr, g_s);
    cudaMemsetAsync(scr, 0, sizeof(Scr));

    K<<<TOTAL_BLOCKS, 256>>>(sem, cl, geo, gd, gg, gr, lbl, inst, out, out_size);
}

// round 14
// speedup vs baseline: 1.0855x; 1.0855x over previous
#include <cuda_runtime.h>
#include <cuda_bf16.h>
#include <math.h>

#define Bn    8
#define Hn    384
#define Wn    384
#define HW    (Hn*Wn)
#define NPIX  (Bn*HW)
#define NCLS  4
#define EDIM  8
#define NINST 33
#define RUNS_PER_IMG (HW/16)          // 9216
#define RUNS_X       (Wn/16)          // 24
#define SEG_BLK_PER_IMG 36
#define SEG_BLOCKS   (SEG_BLK_PER_IMG*Bn)       // 288
#define SEM_BLOCKS   (NPIX/4/256)               // 1152
#define HR_PER_IMG   (RUNS_PER_IMG*2)           // 18432 half-runs
#define K2_BLK_PER_IMG (HR_PER_IMG/256)         // 72
#define K2_BLOCKS    (K2_BLK_PER_IMG*Bn)        // 576
#define TOTAL_BLOCKS (SEG_BLOCKS + SEM_BLOCKS + K2_BLOCKS + 1)

// ---------------- scratch (zero-init at load; self-reset by finalize) --------
struct Scr {
    double sem, a9, a3, a4;
    float  cnt [Bn*NINST];
    float  ws  [Bn*NINST];
    float  ew  [Bn*NINST*EDIM];
    float  pull[Bn*NINST];
    int    done_seg, done_sem, done_k2;
};
__device__ Scr g_s;                                   // static-zero at load
__device__ unsigned int g_runinfo[Bn*RUNS_PER_IMG];   // overwritten each run

__device__ __forceinline__ float warp_redf(float v){
    #pragma unroll
    for (int o = 16; o > 0; o >>= 1) v += __shfl_down_sync(0xffffffffu, v, o);
    return v;
}

__device__ __forceinline__ float bweight(const int* __restrict__ L, int y, int x, int l)
{
    int ym = y > 0 ? y-1 : 0, yp = y < Hn-1 ? y+1 : Hn-1;
    int xm = x > 0 ? x-1 : 0, xp = x < Wn-1 ? x+1 : Wn-1;
    const int* r0 = L + ym*Wn;
    const int* r1 = L + y *Wn;
    const int* r2 = L + yp*Wn;
    bool bd = (r0[xm]!=l) | (r0[x]!=l) | (r0[xp]!=l)
            | (r1[xm]!=l) |              (r1[xp]!=l)
            | (r2[xm]!=l) | (r2[x]!=l) | (r2[xp]!=l);
    return bd ? 10.0f : 1.0f;
}

__device__ __forceinline__ void spin_until(int* ctr, int target)
{
    if (threadIdx.x == 0) {
        while (atomicAdd(ctr, 0) < target) __nanosleep(64);
        __threadfence();
    }
    __syncthreads();
}

__device__ __forceinline__ void signal_done(int* ctr)
{
    __syncthreads();
    if (threadIdx.x == 0) { __threadfence(); atomicAdd(ctr, 1); }
}

__device__ __forceinline__ float l1f4(float4 a, float4 c)
{
    return fabsf(a.x-c.x)+fabsf(a.y-c.y)+fabsf(a.z-c.z)+fabsf(a.w-c.w);
}

// =============================================================================
// One persistent kernel (R12 structure — validated optimum). Roles:
//   [0, SEG)                 : segment sums
//   [SEG, SEG+SEM)           : semantic NLL + affinity L1
//   [SEG+SEM, SEG+SEM+K2B)   : pull term (spin-waits on seg counter)
//   last                     : finalize + scratch reset (self-cleaning graph)
// =============================================================================
__global__ void __launch_bounds__(256, 5)
K(const float* __restrict__ sem, const int* __restrict__ cl,
  const float* __restrict__ geo, const float* __restrict__ gd,
  const float* __restrict__ gg,  const float* __restrict__ gr,
  const int*   __restrict__ lbl, const float* __restrict__ emb,
  float* __restrict__ out, int out_size)
{
    int bid = blockIdx.x;

    // ======================= SEG =============================================
    if (bid < SEG_BLOCKS) {
        int b   = bid / SEG_BLK_PER_IMG;
        int blk = bid - b*SEG_BLK_PER_IMG;

        __shared__ float s_cnt[NINST], s_ws[NINST], s_ew[NINST*EDIM];
        for (int i = threadIdx.x; i < NINST; i += blockDim.x) { s_cnt[i]=0.f; s_ws[i]=0.f; }
        for (int i = threadIdx.x; i < NINST*EDIM; i += blockDim.x) s_ew[i]=0.f;
        __syncthreads();

        const int*   L = lbl + b*HW;
        const float* E = emb + (size_t)b*EDIM*HW;

        int r = blk*blockDim.x + threadIdx.x;
        int y  = r / RUNS_X;
        int x0 = (r - y*RUNS_X) * 16;
        int base = y*Wn + x0;

        const int*  rM = L + base;
        const int4* m4 = (const int4*)rM;
        int4 a0 = m4[0], a1 = m4[1], a2 = m4[2], a3 = m4[3];
        int l = a0.x;
        bool uni = (a0.y==l)&(a0.z==l)&(a0.w==l)
                 & (a1.x==l)&(a1.y==l)&(a1.z==l)&(a1.w==l)
                 & (a2.x==l)&(a2.y==l)&(a2.z==l)&(a2.w==l)
                 & (a3.x==l)&(a3.y==l)&(a3.z==l)&(a3.w==l);

        if (uni) {
            int ym = y > 0 ? y-1 : 0, yp = y < Hn-1 ? y+1 : Hn-1;
            const int* rT = L + ym*Wn + x0;
            const int* rB = L + yp*Wn + x0;
            const int4* t4 = (const int4*)rT;
            const int4* b4 = (const int4*)rB;
            unsigned int bad = 0;
            #pragma unroll
            for (int k = 0; k < 4; k++) {
                int4 tt = t4[k];
                bad |= ((unsigned)(tt.x!=l)<<(1+4*k)) | ((unsigned)(tt.y!=l)<<(2+4*k))
                     | ((unsigned)(tt.z!=l)<<(3+4*k)) | ((unsigned)(tt.w!=l)<<(4+4*k));
                int4 bb = b4[k];
                bad |= ((unsigned)(bb.x!=l)<<(1+4*k)) | ((unsigned)(bb.y!=l)<<(2+4*k))
                     | ((unsigned)(bb.z!=l)<<(3+4*k)) | ((unsigned)(bb.w!=l)<<(4+4*k));
            }
            int xl = (x0 > 0) ? -1 : 0;
            int xr = (x0+16 < Wn) ? 16 : 15;
            bad |= (unsigned)(rT[xl]!=l) | ((unsigned)(rT[xr]!=l)<<17);
            bad |= (unsigned)(rB[xl]!=l) | ((unsigned)(rB[xr]!=l)<<17);
            bad |= (unsigned)(rM[xl]!=l) | ((unsigned)(rM[xr]!=l)<<17);

            unsigned int mask = (bad | (bad>>1) | (bad>>2)) & 0xFFFFu;

            atomicAdd(&s_cnt[l], 16.0f);
            atomicAdd(&s_ws [l], 16.0f + 9.0f*(float)__popc(mask));
            #pragma unroll
            for (int c = 0; c < EDIM; c++) {
                const float4* Ep = (const float4*)(E + (size_t)c*HW + base);
                float4 e0 = Ep[0], e1 = Ep[1], e2 = Ep[2], e3 = Ep[3];
                float ev[16] = {e0.x,e0.y,e0.z,e0.w, e1.x,e1.y,e1.z,e1.w,
                                e2.x,e2.y,e2.z,e2.w, e3.x,e3.y,e3.z,e3.w};
                float acc = 0.f;
                #pragma unroll
                for (int i = 0; i < 16; i++)
                    acc += ev[i] * fmaf((float)((mask>>i)&1u), 9.0f, 1.0f);
                atomicAdd(&s_ew[l*EDIM+c], acc);
            }
            g_runinfo[b*RUNS_PER_IMG + r] = mask | ((unsigned)l<<16) | (1u<<31);
        } else {
            int ls[16] = {a0.x,a0.y,a0.z,a0.w, a1.x,a1.y,a1.z,a1.w,
                          a2.x,a2.y,a2.z,a2.w, a3.x,a3.y,a3.z,a3.w};
            unsigned int mask = 0;
            #pragma unroll 1
            for (int i = 0; i < 16; i++) {
                int li = ls[i];
                float w = bweight(L, y, x0+i, li);
                if (w > 1.f) mask |= (1u<<i);
                atomicAdd(&s_cnt[li], 1.0f);
                atomicAdd(&s_ws [li], w);
                for (int c = 0; c < EDIM; c++)
                    atomicAdd(&s_ew[li*EDIM+c], E[(size_t)c*HW + base + i] * w);
            }
            g_runinfo[b*RUNS_PER_IMG + r] = mask;
        }
        __syncthreads();
        for (int i = threadIdx.x; i < NINST; i += blockDim.x) {
            if (s_cnt[i] != 0.f) atomicAdd(&g_s.cnt[b*NINST+i], s_cnt[i]);
            if (s_ws [i] != 0.f) atomicAdd(&g_s.ws [b*NINST+i], s_ws [i]);
        }
        for (int i = threadIdx.x; i < NINST*EDIM; i += blockDim.x)
            if (s_ew[i] != 0.f) atomicAdd(&g_s.ew[b*NINST*EDIM+i], s_ew[i]);

        signal_done(&g_s.done_seg);
        return;
    }
    bid -= SEG_BLOCKS;

    // ======================= SEMAFF ==========================================
    if (bid < SEM_BLOCKS) {
        int t  = bid*blockDim.x + threadIdx.x;
        int H4 = HW/4;
        int b  = t / H4;
        int q4 = t - b*H4;
        size_t q = (size_t)q4 * 4;

        const float4* s4 = (const float4*)(sem + (size_t)b*NCLS*HW + q);
        float4 x0 = __ldcs(s4);
        float4 x1 = __ldcs(s4 + HW/4);
        float4 x2 = __ldcs(s4 + 2*(HW/4));
        float4 x3 = __ldcs(s4 + 3*(HW/4));
        int4 cc = __ldcs((const int4*)(cl + (size_t)b*HW + q));

        float s = 0.f;
        {
            float a[4][4] = {{x0.x,x1.x,x2.x,x3.x},{x0.y,x1.y,x2.y,x3.y},
                             {x0.z,x1.z,x2.z,x3.z},{x0.w,x1.w,x2.w,x3.w}};
            int   ci[4] = {cc.x, cc.y, cc.z, cc.w};
            #pragma unroll
            for (int j = 0; j < 4; j++) {
                float m = fmaxf(fmaxf(a[j][0],a[j][1]), fmaxf(a[j][2],a[j][3]));
                float sum = __expf(a[j][0]-m)+__expf(a[j][1]-m)
                          + __expf(a[j][2]-m)+__expf(a[j][3]-m);
                float lse = m + __logf(sum);
                int c = ci[j];
                float xc = (c==0) ? a[j][0] : ((c==1) ? a[j][1] : ((c==2) ? a[j][2] : a[j][3]));
                s += lse - xc;
            }
        }

        const float4* gp = (const float4*)(geo + (size_t)b*16*HW + q);
        const float4* dp = (const float4*)(gd  + (size_t)b*9 *HW + q);
        const float4* gp2= (const float4*)(gg  + (size_t)b*3 *HW + q);
        const float4* rp = (const float4*)(gr  + (size_t)b*4 *HW + q);
        float t9 = 0, t3 = 0, t4v = 0;
        #pragma unroll
        for (int i = 0; i < 9; i += 3) {
            float4 a0 = __ldcs(gp + (size_t)(i+0)*(HW/4));
            float4 a1 = __ldcs(gp + (size_t)(i+1)*(HW/4));
            float4 a2 = __ldcs(gp + (size_t)(i+2)*(HW/4));
            float4 c0 = __ldcs(dp + (size_t)(i+0)*(HW/4));
            float4 c1 = __ldcs(dp + (size_t)(i+1)*(HW/4));
            float4 c2 = __ldcs(dp + (size_t)(i+2)*(HW/4));
            t9 += l1f4(a0,c0) + l1f4(a1,c1) + l1f4(a2,c2);
        }
        {
            float4 a0 = __ldcs(gp + (size_t)9 *(HW/4));
            float4 a1 = __ldcs(gp + (size_t)10*(HW/4));
            float4 a2 = __ldcs(gp + (size_t)11*(HW/4));
            float4 c0 = __ldcs(gp2);
            float4 c1 = __ldcs(gp2 + (HW/4));
            float4 c2 = __ldcs(gp2 + 2*(HW/4));
            t3 = l1f4(a0,c0) + l1f4(a1,c1) + l1f4(a2,c2);
        }
        {
            float4 a0 = __ldcs(gp + (size_t)12*(HW/4));
            float4 a1 = __ldcs(gp + (size_t)13*(HW/4));
            float4 a2 = __ldcs(gp + (size_t)14*(HW/4));
            float4 a3 = __ldcs(gp + (size_t)15*(HW/4));
            float4 c0 = __ldcs(rp);
            float4 c1 = __ldcs(rp + (HW/4));
            float4 c2 = __ldcs(rp + 2*(HW/4));
            float4 c3 = __ldcs(rp + 3*(HW/4));
            t4v = l1f4(a0,c0) + l1f4(a1,c1) + l1f4(a2,c2) + l1f4(a3,c3);
        }

        __shared__ float sh[4][8];
        int lane = threadIdx.x & 31, wid = threadIdx.x >> 5;
        float v0 = warp_redf(s);
        float v1 = warp_redf(t9);
        float v2 = warp_redf(t3);
        float v3 = warp_redf(t4v);
        if (lane == 0) { sh[0][wid]=v0; sh[1][wid]=v1; sh[2][wid]=v2; sh[3][wid]=v3; }
        __syncthreads();
        if (wid == 0) {
            v0 = lane < 8 ? sh[0][lane] : 0.f;
            v1 = lane < 8 ? sh[1][lane] : 0.f;
            v2 = lane < 8 ? sh[2][lane] : 0.f;
            v3 = lane < 8 ? sh[3][lane] : 0.f;
            v0 = warp_redf(v0); v1 = warp_redf(v1); v2 = warp_redf(v2); v3 = warp_redf(v3);
            if (lane == 0) {
                atomicAdd(&g_s.sem, (double)v0); atomicAdd(&g_s.a9, (double)v1);
                atomicAdd(&g_s.a3, (double)v2);  atomicAdd(&g_s.a4, (double)v3);
            }
        }
        signal_done(&g_s.done_sem);
        return;
    }
    bid -= SEM_BLOCKS;

    // ======================= PULL (waits on seg) =============================
    if (bid < K2_BLOCKS) {
        spin_until(&g_s.done_seg, SEG_BLOCKS);

        int b   = bid / K2_BLK_PER_IMG;
        int blk = bid - b*K2_BLK_PER_IMG;

        __shared__ float s_ctr[NINST*EDIM];
        __shared__ float s_pull[NINST];
        for (int i = threadIdx.x; i < NINST*EDIM; i += blockDim.x)
            s_ctr[i] = g_s.ew[b*NINST*EDIM + i] / (g_s.ws[b*NINST + (i>>3)] + 1e-8f);
        for (int i = threadIdx.x; i < NINST; i += blockDim.x) s_pull[i] = 0.f;
        __syncthreads();

        const float* E = emb + (size_t)b*EDIM*HW;

        int r8 = blk*blockDim.x + threadIdx.x;
        int y  = r8 / (2*RUNS_X);
        int x8 = (r8 - y*(2*RUNS_X)) * 8;
        int base = y*Wn + x8;

        unsigned int info = g_runinfo[b*RUNS_PER_IMG + y*RUNS_X + (x8>>4)];
        unsigned int mask8 = (info >> (((x8>>3)&1)*8)) & 0xFFu;

        if (info & (1u<<31)) {
            int l = (int)((info>>16) & 0x3Fu);
            float ss[8];
            #pragma unroll
            for (int i = 0; i < 8; i++) ss[i] = 0.f;
            #pragma unroll
            for (int c = 0; c < EDIM; c++) {
                float ccv = s_ctr[l*EDIM+c];
                const float4* Ep = (const float4*)(E + (size_t)c*HW + base);
                float4 e0 = Ep[0], e1 = Ep[1];
                float d0=e0.x-ccv, d1=e0.y-ccv, d2=e0.z-ccv, d3=e0.w-ccv;
                float d4=e1.x-ccv, d5=e1.y-ccv, d6=e1.z-ccv, d7=e1.w-ccv;
                ss[0]+=d0*d0; ss[1]+=d1*d1; ss[2]+=d2*d2; ss[3]+=d3*d3;
                ss[4]+=d4*d4; ss[5]+=d5*d5; ss[6]+=d6*d6; ss[7]+=d7*d7;
            }
            float acc = 0.f;
            #pragma unroll
            for (int i = 0; i < 8; i++) {
                float dist = sqrtf(fmaxf(ss[i], 1e-12f));
                float t = fmaxf(dist - 0.5f, 0.f);
                float w = fmaf((float)((mask8>>i)&1u), 9.0f, 1.0f);
                acc += t*t*w;
            }
            atomicAdd(&s_pull[l], acc);
        } else {
            const int* Lp = lbl + b*HW + base;
            int4 L0 = ((const int4*)Lp)[0];
            int4 L1 = ((const int4*)Lp)[1];
            int ls[8] = {L0.x,L0.y,L0.z,L0.w, L1.x,L1.y,L1.z,L1.w};
            #pragma unroll 1
            for (int i = 0; i < 8; i++) {
                int l = ls[i];
                float ssv = 0.f;
                for (int c = 0; c < EDIM; c++) {
                    float d = E[(size_t)c*HW + base + i] - s_ctr[l*EDIM+c];
                    ssv += d*d;
                }
                float dist = sqrtf(fmaxf(ssv, 1e-12f));
                float t = fmaxf(dist - 0.5f, 0.f);
                float w = fmaf((float)((mask8>>i)&1u), 9.0f, 1.0f);
                atomicAdd(&s_pull[l], t*t*w);
            }
        }
        __syncthreads();
        for (int i = threadIdx.x; i < NINST; i += blockDim.x)
            if (s_pull[i] != 0.f) atomicAdd(&g_s.pull[b*NINST+i], s_pull[i]);

        signal_done(&g_s.done_k2);
        return;
    }

    // ======================= FINALIZE ========================================
    spin_until(&g_s.done_sem, SEM_BLOCKS);
    spin_until(&g_s.done_k2,  K2_BLOCKS);

    __shared__ float s_ctr[Bn][NINST*EDIM];
    __shared__ float s_cnt[Bn][NINST];
    __shared__ float rp[Bn], rq[Bn], rn[Bn];
    __shared__ int   rpres[Bn];

    for (int i = threadIdx.x; i < Bn*NINST*EDIM; i += blockDim.x) {
        int b = i / (NINST*EDIM), k = i % (NINST*EDIM);
        s_ctr[b][k] = g_s.ew[i] / (g_s.ws[b*NINST + (k>>3)] + 1e-8f);
    }
    for (int i = threadIdx.x; i < Bn*NINST; i += blockDim.x)
        s_cnt[i/NINST][i%NINST] = g_s.cnt[i];
    __syncthreads();

    int wid = threadIdx.x >> 5, lane = threadIdx.x & 31;
    if (wid < Bn) {
        int b = wid;
        float pull = 0, norm = 0; int np = 0;
        for (int k = lane; k < NINST; k += 32) {
            bool pres = (k > 0) && (s_cnt[b][k] > 0.f);
            if (pres) {
                pull += g_s.pull[b*NINST+k] / fmaxf(s_cnt[b][k], 1.0f);
                float ssn = 0;
                #pragma unroll
                for (int c = 0; c < EDIM; c++) { float v = s_ctr[b][k*EDIM+c]; ssn += v*v; }
                norm += sqrtf(fmaxf(ssn, 1e-12f));
                np++;
            }
        }
        float push = 0; int npair = 0;
        for (int idx = lane; idx < NINST*NINST; idx += 32) {
            int i = idx / NINST, j = idx % NINST;
            if (j > i && i > 0 && s_cnt[b][i] > 0.f && s_cnt[b][j] > 0.f) {
                float ssd = 0;
                #pragma unroll
                for (int c = 0; c < EDIM; c++) {
                    float d = s_ctr[b][i*EDIM+c] - s_ctr[b][j*EDIM+c];
                    ssd += d*d;
                }
                float pd = sqrtf(fmaxf(ssd, 1e-12f));
                float t = fmaxf(3.0f - pd, 0.f);
                push += t*t; npair++;
            }
        }
        pull = warp_redf(pull); norm = warp_redf(norm); push = warp_redf(push);
        np   = __reduce_add_sync(0xffffffffu, np);
        npair= __reduce_add_sync(0xffffffffu, npair);
        if (lane == 0) {
            rp[b] = pull;
            rq[b] = push / fmaxf((float)npair, 1.0f);
            rn[b] = norm / fmaxf((float)np, 1.0f);
            rpres[b] = (np > 0) ? 1 : 0;
        }
    }
    __syncthreads();
    if (threadIdx.x == 0) {
        float pull = 0, push = 0, norm = 0; int n = 0;
        for (int bb = 0; bb < Bn; bb++) { pull += rp[bb]; push += rq[bb]; norm += rn[bb]; n += rpres[bb]; }
        float nn  = fmaxf((float)n, 1.0f);
        float ins = (pull + push + 0.001f*norm) / nn;
        float semv = (float)(g_s.sem / (double)NPIX);
        float aff  = (float)(g_s.a9/(double)((size_t)Bn*9*HW)
                           + g_s.a3/(double)((size_t)Bn*3*HW)
                           + g_s.a4/(double)((size_t)Bn*4*HW));
        out[0] = semv + aff + ins;
        if (out_size > 1) out[1] = semv;
        if (out_size > 2) out[2] = aff;
        if (out_size > 3) out[3] = ins;
    }

    // ---- self-reset scratch for the next graph replay (this block is provably
    //      last: every producer signaled before our spins passed) ------------
    __syncthreads();
    {
        float* f = (float*)&g_s.cnt[0];
        const int nf = (Bn*NINST)*3 + Bn*NINST*EDIM;   // cnt, ws, pull, ew
        for (int i = threadIdx.x; i < nf; i += blockDim.x)
            ((float*)&g_s.cnt[0])[i] = 0.f;            // contiguous: cnt,ws,ew,pull
        (void)f;
        if (threadIdx.x == 0) {
            g_s.sem = 0.0; g_s.a9 = 0.0; g_s.a3 = 0.0; g_s.a4 = 0.0;
            g_s.done_seg = 0; g_s.done_sem = 0; g_s.done_k2 = 0;
            __threadfence();
        }
    }
}

// ---------------- entry -------------------------------------------------------
extern "C" void kernel_launch(void* const* d_in, const int* in_sizes, int n_in,
                              void* d_out, int out_size)
{
    const float* sem  = (const float*)d_in[0];
    const int*   cl   = (const int*)  d_in[1];
    const float* inst = (const float*)d_in[2];
    const float* geo  = (const float*)d_in[3];
    const float* gd   = (const float*)d_in[4];
    const float* gg   = (const float*)d_in[5];
    const float* gr   = (const float*)d_in[6];
    const int*   lbl  = (const int*)  d_in[7];
    float* out = (float*)d_out;

    // No memset: __device__ globals are zero-initialized at module load and the
    // finalize block resets all scratch at the end of every run (self-cleaning).
    K<<<TOTAL_BLOCKS, 256>>>(sem, cl, geo, gd, gg, gr, lbl, inst, out, out_size);
}